// round 11
// baseline (speedup 1.0000x reference)
#include <cuda_runtime.h>
#include <cstdint>

#define BATCH 256
#define FEAT_DIM 512
#define NUM_CLASSES 85742

#define FX_SCALE 16777216.0f          // 2^24 fixed-point scale
#define FX_MASK  ((1ULL << 48) - 1ULL)
#define CNT_ONE  (1ULL << 48)
// 1 / (FX_SCALE * BATCH) as a single fp32 constant (exact power of two: 2^-32)
#define INV_SCALE_BATCH 2.3283064365386963e-10f

// Packed accumulator: bits [48..] = arrival count, bits [0..48) = fixed-point sum.
// Zero-initialized device global; completing warp resets it (graph-replay safe).
__device__ unsigned long long g_acc;

// 256 blocks x 32 threads: one warp per batch row, spread across all 148 SMs
// (1-2 warps per SM => minimal L1tex queueing). No block syncs, no smem.
// Critical path: epoch1 (labels + x, parallel) -> epoch2 (center gather) ->
// shfl reduce -> one packed ATOMG. Measured at the latency roofline.
__global__ __launch_bounds__(32) void center_loss_warprow_kernel(
    const float* __restrict__ x,
    const int*   __restrict__ labels_i32,
    const float* __restrict__ centers,
    float*       __restrict__ out)
{
    const int lane = threadIdx.x;
    const int row  = blockIdx.x;

    // ---- Batch 1: all label-independent loads (label candidates + x row). ----
    const int2* l2 = reinterpret_cast<const int2*>(labels_i32);
    int2 det   = __ldg(&l2[lane]);        // detection words [2*lane, 2*lane+1]
    int2 c64   = __ldg(&l2[row]);         // i64 layout: element `row` = {low, high}
    int2 c32p  = __ldg(&l2[row >> 1]);    // i32 layout: element `row` is in this pair

    const float4* xr = reinterpret_cast<const float4*>(x) + (size_t)row * (FEAT_DIM / 4);
    float4 xv0 = __ldg(&xr[lane]);
    float4 xv1 = __ldg(&xr[lane + 32]);
    float4 xv2 = __ldg(&xr[lane + 64]);
    float4 xv3 = __ldg(&xr[lane + 96]);

    // int64 little-endian with labels < 2^17 => words are [lbl,0,lbl,0,...].
    // 32 random int32 labels in [0, 85742) cannot all have odd words zero.
    // All warps test the SAME 64 words => globally consistent decision.
    bool ok = (det.y == 0) && (det.x >= 0) && (det.x < NUM_CLASSES);
    bool is_i64 = __all_sync(0xFFFFFFFFu, ok);
    const int c32 = (row & 1) ? c32p.y : c32p.x;
    const int lbl = is_i64 ? c64.x : c32;

    // ---- Batch 2: gather center row (the only serial dependency). ----
    const float4* cr = reinterpret_cast<const float4*>(centers) + (size_t)lbl * (FEAT_DIM / 4);
    float4 cv0 = __ldg(&cr[lane]);
    float4 cv1 = __ldg(&cr[lane + 32]);
    float4 cv2 = __ldg(&cr[lane + 64]);
    float4 cv3 = __ldg(&cr[lane + 96]);

    float s = 0.0f;
    {
        float d;
        d = xv0.x - cv0.x; s += d * d;  d = xv0.y - cv0.y; s += d * d;
        d = xv0.z - cv0.z; s += d * d;  d = xv0.w - cv0.w; s += d * d;
        d = xv1.x - cv1.x; s += d * d;  d = xv1.y - cv1.y; s += d * d;
        d = xv1.z - cv1.z; s += d * d;  d = xv1.w - cv1.w; s += d * d;
        d = xv2.x - cv2.x; s += d * d;  d = xv2.y - cv2.y; s += d * d;
        d = xv2.z - cv2.z; s += d * d;  d = xv2.w - cv2.w; s += d * d;
        d = xv3.x - cv3.x; s += d * d;  d = xv3.y - cv3.y; s += d * d;
        d = xv3.z - cv3.z; s += d * d;  d = xv3.w - cv3.w; s += d * d;
    }

    #pragma unroll
    for (int off = 16; off > 0; off >>= 1)
        s += __shfl_xor_sync(0xFFFFFFFFu, s, off);

    if (lane == 0) {
        float dist = fminf(fmaxf(s, 1e-12f), 1e12f);
        // Deterministic accumulation: integer fixed-point, order-independent.
        unsigned long long add = CNT_ONE + __float2ull_rn(dist * FX_SCALE);
        unsigned long long old = atomicAdd(&g_acc, add);
        if ((old >> 48) == (BATCH - 1)) {
            unsigned long long total = (old + add) & FX_MASK;
            out[0] = (float)total * INV_SCALE_BATCH;
            // All 256 arrivals observed; plain store reset is race-free and
            // cheaper than atomicExch on the kernel-retire path.
            g_acc = 0ULL;
        }
    }
}

extern "C" void kernel_launch(void* const* d_in, const int* in_sizes, int n_in,
                              void* d_out, int out_size)
{
    // Identify inputs by UNIQUE element counts (order-proof):
    //   x: 131072, labels: 256, centers: 43899904
    const float* x = nullptr;
    const int*   labels_i32 = nullptr;
    const float* centers = nullptr;

    for (int i = 0; i < n_in; ++i) {
        if (in_sizes[i] == BATCH * FEAT_DIM)   x = (const float*)d_in[i];
        else if (in_sizes[i] == BATCH)         labels_i32 = (const int*)d_in[i];
        else                                   centers = (const float*)d_in[i];
    }

    center_loss_warprow_kernel<<<BATCH, 32>>>(x, labels_i32, centers, (float*)d_out);
}

// round 12
// speedup vs baseline: 1.0386x; 1.0386x over previous
#include <cuda_runtime.h>
#include <cstdint>

#define BATCH 256
#define FEAT_DIM 512
#define NUM_CLASSES 85742

#define FX_SCALE 16777216.0f          // 2^24 fixed-point scale
#define FX_MASK  ((1ULL << 48) - 1ULL)
#define CNT_ONE  (1ULL << 48)
// 1 / (FX_SCALE * BATCH) as a single fp32 constant (exact power of two: 2^-32)
#define INV_SCALE_BATCH 2.3283064365386963e-10f

// Packed accumulator: bits [48..] = arrival count, bits [0..48) = fixed-point sum.
// Zero-initialized device global; completing warp resets it (graph-replay safe).
__device__ unsigned long long g_acc;

// 256 blocks x 32 threads: one warp per batch row, spread across all 148 SMs
// (1-2 warps per SM => minimal L1tex queueing). No block syncs, no smem.
// Critical path: epoch1 (labels + x, parallel) -> epoch2 (center gather) ->
// shfl reduce -> one packed ATOMG. Measured at the latency roofline.
__global__ __launch_bounds__(32) void center_loss_warprow_kernel(
    const float* __restrict__ x,
    const int*   __restrict__ labels_i32,
    const float* __restrict__ centers,
    float*       __restrict__ out)
{
    const int lane = threadIdx.x;
    const int row  = blockIdx.x;

    // ---- Batch 1: all label-independent loads (label candidates + x row). ----
    const int2* l2 = reinterpret_cast<const int2*>(labels_i32);
    int2 det   = __ldg(&l2[lane]);        // detection words [2*lane, 2*lane+1]
    int2 c64   = __ldg(&l2[row]);         // i64 layout: element `row` = {low, high}
    int2 c32p  = __ldg(&l2[row >> 1]);    // i32 layout: element `row` is in this pair

    const float4* xr = reinterpret_cast<const float4*>(x) + (size_t)row * (FEAT_DIM / 4);
    float4 xv0 = __ldg(&xr[lane]);
    float4 xv1 = __ldg(&xr[lane + 32]);
    float4 xv2 = __ldg(&xr[lane + 64]);
    float4 xv3 = __ldg(&xr[lane + 96]);

    // int64 little-endian with labels < 2^17 => words are [lbl,0,lbl,0,...].
    // 32 random int32 labels in [0, 85742) cannot all have odd words zero.
    // All warps test the SAME 64 words => globally consistent decision.
    bool ok = (det.y == 0) && (det.x >= 0) && (det.x < NUM_CLASSES);
    bool is_i64 = __all_sync(0xFFFFFFFFu, ok);
    const int c32 = (row & 1) ? c32p.y : c32p.x;
    const int lbl = is_i64 ? c64.x : c32;

    // ---- Batch 2: gather center row (the only serial dependency). ----
    const float4* cr = reinterpret_cast<const float4*>(centers) + (size_t)lbl * (FEAT_DIM / 4);
    float4 cv0 = __ldg(&cr[lane]);
    float4 cv1 = __ldg(&cr[lane + 32]);
    float4 cv2 = __ldg(&cr[lane + 64]);
    float4 cv3 = __ldg(&cr[lane + 96]);

    float s = 0.0f;
    {
        float d;
        d = xv0.x - cv0.x; s += d * d;  d = xv0.y - cv0.y; s += d * d;
        d = xv0.z - cv0.z; s += d * d;  d = xv0.w - cv0.w; s += d * d;
        d = xv1.x - cv1.x; s += d * d;  d = xv1.y - cv1.y; s += d * d;
        d = xv1.z - cv1.z; s += d * d;  d = xv1.w - cv1.w; s += d * d;
        d = xv2.x - cv2.x; s += d * d;  d = xv2.y - cv2.y; s += d * d;
        d = xv2.z - cv2.z; s += d * d;  d = xv2.w - cv2.w; s += d * d;
        d = xv3.x - cv3.x; s += d * d;  d = xv3.y - cv3.y; s += d * d;
        d = xv3.z - cv3.z; s += d * d;  d = xv3.w - cv3.w; s += d * d;
    }

    #pragma unroll
    for (int off = 16; off > 0; off >>= 1)
        s += __shfl_xor_sync(0xFFFFFFFFu, s, off);

    if (lane == 0) {
        float dist = fminf(fmaxf(s, 1e-12f), 1e12f);
        // Deterministic accumulation: integer fixed-point, order-independent.
        unsigned long long add = CNT_ONE + __float2ull_rn(dist * FX_SCALE);
        unsigned long long old = atomicAdd(&g_acc, add);
        if ((old >> 48) == (BATCH - 1)) {
            unsigned long long total = (old + add) & FX_MASK;
            out[0] = (float)total * INV_SCALE_BATCH;
            // All 256 arrivals observed; plain store reset is race-free and
            // cheaper than atomicExch on the kernel-retire path.
            g_acc = 0ULL;
        }
    }
}

extern "C" void kernel_launch(void* const* d_in, const int* in_sizes, int n_in,
                              void* d_out, int out_size)
{
    // Identify inputs by UNIQUE element counts (order-proof):
    //   x: 131072, labels: 256, centers: 43899904
    const float* x = nullptr;
    const int*   labels_i32 = nullptr;
    const float* centers = nullptr;

    for (int i = 0; i < n_in; ++i) {
        if (in_sizes[i] == BATCH * FEAT_DIM)   x = (const float*)d_in[i];
        else if (in_sizes[i] == BATCH)         labels_i32 = (const int*)d_in[i];
        else                                   centers = (const float*)d_in[i];
    }

    center_loss_warprow_kernel<<<BATCH, 32>>>(x, labels_i32, centers, (float*)d_out);
}